// round 3
// baseline (speedup 1.0000x reference)
#include <cuda_runtime.h>
#include <cstdint>

// Problem constants (fixed shapes per reference)
#define P_POINTS   1500000
#define TOTAL_BEV  40000
#define NCH        80
#define NCH4       20          // 80 channels as float4

// Scratch (no cudaMalloc allowed)
__device__ int g_is64;                     // 1 if index arrays are int64, 0 if int32
__device__ int g_seg[TOTAL_BEV + 1];       // segment boundaries: seg[b] = lower_bound(ranks_bev, b)

// ---------------------------------------------------------------------------
// Kernel 1: detect index dtype. Values are < 2^31, so when read as u64 the
// high 32 bits are zero iff the data is really int64. If it's int32, the high
// word is the NEXT (random, almost surely nonzero) element.
// ---------------------------------------------------------------------------
__global__ void detect_dtype_kernel(const unsigned long long* __restrict__ rd_u64) {
    unsigned long long hi = 0ULL;
#pragma unroll
    for (int i = 0; i < 8; ++i) hi |= (rd_u64[i] >> 32);
    g_is64 = (hi == 0ULL) ? 1 : 0;
}

__device__ __forceinline__ long long ld_idx(const void* __restrict__ p, int i, int is64) {
    if (is64) return __ldg((const long long*)p + i);
    return (long long)__ldg((const int*)p + i);
}

// ---------------------------------------------------------------------------
// Kernel 2: per-bin lower_bound over sorted ranks_bev (L2-resident, 12 MB max)
// ---------------------------------------------------------------------------
__global__ void build_seg_kernel(const void* __restrict__ ranks_bev) {
    int b = blockIdx.x * blockDim.x + threadIdx.x;
    if (b > TOTAL_BEV) return;
    const int is64 = g_is64;
    int lo = 0, hi = P_POINTS;
    while (lo < hi) {
        int m = (lo + hi) >> 1;
        long long v = ld_idx(ranks_bev, m, is64);
        if (v < (long long)b) lo = m + 1; else hi = m;
    }
    g_seg[b] = lo;
}

// ---------------------------------------------------------------------------
// Kernel 3: one warp per BEV bin. Lanes 0..19 each accumulate a float4 slice
// of the 80-channel row. Per-point index/depth loads are warp-uniform
// (broadcast). Unroll-by-2 over points for MLP.
// ---------------------------------------------------------------------------
__global__ void __launch_bounds__(256) bev_pool_kernel(
    const float* __restrict__ depth,       // [498432]
    const float* __restrict__ feat,        // [4224, 80]
    const void* __restrict__ ranks_depth,  // [P]
    const void* __restrict__ ranks_feat,   // [P]
    float* __restrict__ out)               // [40000, 80]
{
    const int warp = (blockIdx.x * blockDim.x + threadIdx.x) >> 5;
    const int lane = threadIdx.x & 31;
    if (warp >= TOTAL_BEV) return;

    const int is64 = g_is64;
    const int lo = g_seg[warp];
    const int hi = g_seg[warp + 1];

    const int  active = (lane < NCH4);
    const int  c4     = active ? lane : 0;     // inactive lanes shadow lane 0 (same cache line)
    const float4* __restrict__ fv = (const float4*)feat;

    float4 acc = make_float4(0.f, 0.f, 0.f, 0.f);

    int p = lo;
    for (; p + 1 < hi; p += 2) {
        long long rd0 = ld_idx(ranks_depth, p,     is64);
        long long rd1 = ld_idx(ranks_depth, p + 1, is64);
        long long rf0 = ld_idx(ranks_feat,  p,     is64);
        long long rf1 = ld_idx(ranks_feat,  p + 1, is64);
        float d0 = __ldg(depth + rd0);
        float d1 = __ldg(depth + rd1);
        float4 f0 = __ldg(fv + rf0 * NCH4 + c4);
        float4 f1 = __ldg(fv + rf1 * NCH4 + c4);
        acc.x = fmaf(f0.x, d0, acc.x); acc.y = fmaf(f0.y, d0, acc.y);
        acc.z = fmaf(f0.z, d0, acc.z); acc.w = fmaf(f0.w, d0, acc.w);
        acc.x = fmaf(f1.x, d1, acc.x); acc.y = fmaf(f1.y, d1, acc.y);
        acc.z = fmaf(f1.z, d1, acc.z); acc.w = fmaf(f1.w, d1, acc.w);
    }
    if (p < hi) {
        long long rd0 = ld_idx(ranks_depth, p, is64);
        long long rf0 = ld_idx(ranks_feat,  p, is64);
        float d0 = __ldg(depth + rd0);
        float4 f0 = __ldg(fv + rf0 * NCH4 + c4);
        acc.x = fmaf(f0.x, d0, acc.x); acc.y = fmaf(f0.y, d0, acc.y);
        acc.z = fmaf(f0.z, d0, acc.z); acc.w = fmaf(f0.w, d0, acc.w);
    }

    if (active) {
        ((float4*)out)[(size_t)warp * NCH4 + c4] = acc;  // empty bins write zeros
    }
}

// ---------------------------------------------------------------------------
// Launch: inputs (metadata order) = depth, feat, ranks_depth, ranks_feat,
// ranks_bev, interval_starts, interval_lengths, [total_bev]
// interval_* are unused by the reference (segments come from sorted ranks_bev).
// ---------------------------------------------------------------------------
extern "C" void kernel_launch(void* const* d_in, const int* in_sizes, int n_in,
                              void* d_out, int out_size) {
    const float* depth       = (const float*)d_in[0];
    const float* feat        = (const float*)d_in[1];
    const void*  ranks_depth = (const void*)d_in[2];
    const void*  ranks_feat  = (const void*)d_in[3];
    const void*  ranks_bev   = (const void*)d_in[4];
    float*       out         = (float*)d_out;

    detect_dtype_kernel<<<1, 1>>>((const unsigned long long*)ranks_depth);

    build_seg_kernel<<<(TOTAL_BEV + 1 + 255) / 256, 256>>>(ranks_bev);

    // one warp per bin: 40000 warps, 8 warps/block -> 5000 blocks
    bev_pool_kernel<<<(TOTAL_BEV * 32 + 255) / 256, 256>>>(
        depth, feat, ranks_depth, ranks_feat, out);
}

// round 4
// speedup vs baseline: 1.0852x; 1.0852x over previous
#include <cuda_runtime.h>
#include <cstdint>

// Problem constants (fixed shapes per reference)
#define P_POINTS   1500000
#define TOTAL_BEV  40000
#define NCH        80
#define NCH4       20          // 80 channels as float4

// Scratch (no cudaMalloc allowed)
__device__ int g_seg[TOTAL_BEV + 1];   // seg[b] = lower_bound(ranks_bev, b)

// ---------------------------------------------------------------------------
// Dtype detection, inlined: index values are < 2^31, so when the buffer is
// really int64 the high 32 bits of the first 4 u64 words are all zero. If the
// data is int32, each "high word" is a random index (P(0) ~ 2e-6 per word).
// Uniform addresses -> L1-hit broadcast, ~free.
// ---------------------------------------------------------------------------
__device__ __forceinline__ int detect64(const void* __restrict__ rd) {
    const unsigned long long* u = (const unsigned long long*)rd;
    unsigned long long h = (__ldg(u + 0) >> 32) | (__ldg(u + 1) >> 32) |
                           (__ldg(u + 2) >> 32) | (__ldg(u + 3) >> 32);
    return h == 0ULL;
}

// All index values fit comfortably in int32 (max 498431).
__device__ __forceinline__ int ld_idx32(const void* __restrict__ p, int i, int is64) {
    if (is64) return (int)__ldg((const long long*)p + i);
    return __ldg((const int*)p + i);
}

// ---------------------------------------------------------------------------
// Kernel 1: per-bin lower_bound over sorted ranks_bev.
// ranks_bev is sorted-uniform, so lower_bound(b) ~ b*P/B with sd <~ 620.
// Bracket around the interpolation guess (w=2048 covers >3 sigma), widen on
// the rare miss, then an 11-step binary search. ~13 dependent L2 loads vs 21.
// ---------------------------------------------------------------------------
__global__ void build_seg_kernel(const void* __restrict__ ranks_bev,
                                 const void* __restrict__ ranks_depth) {
    int b = blockIdx.x * blockDim.x + threadIdx.x;
    if (b > TOTAL_BEV) return;
    const int is64 = detect64(ranks_depth);

    long long guess = (long long)b * P_POINTS / TOTAL_BEV;
    int lo = 0, hi = P_POINTS;
    int w = 2048;
    while (w < P_POINTS) {
        int l = (int)guess - w; if (l < 0) l = 0;
        int h = (int)guess + w; if (h > P_POINTS) h = P_POINTS;
        // lower_bound(b) >= l  iff  l==0 or a[l-1] < b
        // lower_bound(b) <= h  iff  h==P or a[h] >= b
        bool okL = (l == 0)        || (ld_idx32(ranks_bev, l - 1, is64) < b);
        bool okR = (h == P_POINTS) || (ld_idx32(ranks_bev, h,     is64) >= b);
        if (okL && okR) { lo = l; hi = h; break; }
        w <<= 2;
    }
    while (lo < hi) {
        int m = (lo + hi) >> 1;
        if (ld_idx32(ranks_bev, m, is64) < b) lo = m + 1; else hi = m;
    }
    g_seg[b] = lo;
}

// ---------------------------------------------------------------------------
// Kernel 2: one warp per BEV bin. Lanes 0..19 each own a float4 slice of the
// 80-channel row. Points are consumed 4 at a time: each lane loads the indices
// and depth of point p + (lane & 3) -- coalesced (1 wavefront per index array
// per quad instead of 8 uniform wavefronts) -- then width-4 shuffles broadcast
// (depth_j, rf_j) to the whole warp. Feat loads have MLP=4 per iteration.
// ---------------------------------------------------------------------------
__global__ void __launch_bounds__(256) bev_pool_kernel(
    const float* __restrict__ depth,       // [498432]
    const float* __restrict__ feat,        // [4224, 80]
    const void* __restrict__ ranks_depth,  // [P]
    const void* __restrict__ ranks_feat,   // [P]
    float* __restrict__ out)               // [40000, 80]
{
    const int warp = (blockIdx.x * blockDim.x + threadIdx.x) >> 5;
    const int lane = threadIdx.x & 31;
    if (warp >= TOTAL_BEV) return;

    const int is64 = detect64(ranks_depth);
    const int lo = g_seg[warp];
    const int hi = g_seg[warp + 1];

    const int  active = (lane < NCH4);
    const int  c4     = active ? lane : 0;   // idle lanes shadow lane 0's sector
    const int  sub    = lane & 3;
    const float4* __restrict__ fv = (const float4*)feat;

    float4 acc = make_float4(0.f, 0.f, 0.f, 0.f);

    int p = lo;
    // quad loop: 4 points per iteration
    for (; p + 4 <= hi; p += 4) {
        int   rd = ld_idx32(ranks_depth, p + sub, is64);
        int   rf = ld_idx32(ranks_feat,  p + sub, is64);
        float d  = __ldg(depth + rd);
#pragma unroll
        for (int j = 0; j < 4; ++j) {
            float dj  = __shfl_sync(0xffffffffu, d,  j, 4);
            int   rfj = __shfl_sync(0xffffffffu, rf, j, 4);
            float4 f = __ldg(fv + (size_t)rfj * NCH4 + c4);
            acc.x = fmaf(f.x, dj, acc.x); acc.y = fmaf(f.y, dj, acc.y);
            acc.z = fmaf(f.z, dj, acc.z); acc.w = fmaf(f.w, dj, acc.w);
        }
    }
    // remainder (0..3 points), warp-uniform loads
    for (; p < hi; ++p) {
        int   rd = ld_idx32(ranks_depth, p, is64);
        int   rf = ld_idx32(ranks_feat,  p, is64);
        float d  = __ldg(depth + rd);
        float4 f = __ldg(fv + (size_t)rf * NCH4 + c4);
        acc.x = fmaf(f.x, d, acc.x); acc.y = fmaf(f.y, d, acc.y);
        acc.z = fmaf(f.z, d, acc.z); acc.w = fmaf(f.w, d, acc.w);
    }

    if (active) {
        ((float4*)out)[(size_t)warp * NCH4 + c4] = acc;  // empty bins write zeros
    }
}

// ---------------------------------------------------------------------------
// Launch: inputs (metadata order) = depth, feat, ranks_depth, ranks_feat,
// ranks_bev, interval_starts, interval_lengths, [total_bev]
// interval_* are unused by the reference (segments come from sorted ranks_bev).
// ---------------------------------------------------------------------------
extern "C" void kernel_launch(void* const* d_in, const int* in_sizes, int n_in,
                              void* d_out, int out_size) {
    const float* depth       = (const float*)d_in[0];
    const float* feat        = (const float*)d_in[1];
    const void*  ranks_depth = (const void*)d_in[2];
    const void*  ranks_feat  = (const void*)d_in[3];
    const void*  ranks_bev   = (const void*)d_in[4];
    float*       out         = (float*)d_out;

    build_seg_kernel<<<(TOTAL_BEV + 1 + 255) / 256, 256>>>(ranks_bev, ranks_depth);

    // one warp per bin: 40000 warps, 8 warps/block -> 5000 blocks
    bev_pool_kernel<<<(TOTAL_BEV * 32 + 255) / 256, 256>>>(
        depth, feat, ranks_depth, ranks_feat, out);
}

// round 6
// speedup vs baseline: 1.2774x; 1.1771x over previous
#include <cuda_runtime.h>
#include <cstdint>

// Problem constants (fixed shapes per reference)
#define P_POINTS   1500000
#define TOTAL_BEV  40000
#define NCH        80
#define NCH4       20          // 80 channels as float4
#define BATCH      32          // points staged per warp iteration
#define WPB        8           // warps per block (256 threads)

// Scratch (no cudaMalloc allowed)
__device__ int g_seg[TOTAL_BEV + 1];   // seg[b] = lower_bound(ranks_bev, b)

// ---------------------------------------------------------------------------
// Dtype detection, inlined: index values are < 2^31, so when the buffer is
// really int64 the high 32 bits of the first 4 u64 words are all zero. If the
// data is int32, each "high word" is a random index (P(0) ~ 2e-6 per word).
// ---------------------------------------------------------------------------
__device__ __forceinline__ int detect64(const void* __restrict__ rd) {
    const unsigned long long* u = (const unsigned long long*)rd;
    unsigned long long h = (__ldg(u + 0) >> 32) | (__ldg(u + 1) >> 32) |
                           (__ldg(u + 2) >> 32) | (__ldg(u + 3) >> 32);
    return h == 0ULL;
}

// All index values fit in int32 (max 498431).
__device__ __forceinline__ int ld_idx32(const void* __restrict__ p, int i, int is64) {
    if (is64) return (int)__ldg((const long long*)p + i);
    return __ldg((const int*)p + i);
}

// ---------------------------------------------------------------------------
// Kernel 1: per-bin lower_bound over sorted ranks_bev.
// ranks_bev is sorted-uniform: lower_bound(b) ~ b*P/B, sd <~ 620. Bracket
// around the interpolation guess (w=2048 > 3 sigma), widen on rare miss, then
// an 11-step binary search.
// ---------------------------------------------------------------------------
__global__ void build_seg_kernel(const void* __restrict__ ranks_bev,
                                 const void* __restrict__ ranks_depth) {
    int b = blockIdx.x * blockDim.x + threadIdx.x;
    if (b > TOTAL_BEV) return;
    const int is64 = detect64(ranks_depth);

    long long guess = (long long)b * P_POINTS / TOTAL_BEV;
    int lo = 0, hi = P_POINTS;
    int w = 2048;
    while (w < P_POINTS) {
        int l = (int)guess - w; if (l < 0) l = 0;
        int h = (int)guess + w; if (h > P_POINTS) h = P_POINTS;
        bool okL = (l == 0)        || (ld_idx32(ranks_bev, l - 1, is64) < b);
        bool okR = (h == P_POINTS) || (ld_idx32(ranks_bev, h,     is64) >= b);
        if (okL && okR) { lo = l; hi = h; break; }
        w <<= 2;
    }
    while (lo < hi) {
        int m = (lo + hi) >> 1;
        if (ld_idx32(ranks_bev, m, is64) < b) lo = m + 1; else hi = m;
    }
    g_seg[b] = lo;
}

// ---------------------------------------------------------------------------
// Kernel 2: one warp per BEV bin, smem-packed staging.
//   Stage phase (all 32 lanes useful): lane loads (rd, rf) for point p+lane
//   coalesced, gathers d = depth[rd] (the one irreducible random wavefront
//   per point), packs (d, rf) into a u64 and stores to the warp's smem slot.
//   Consume phase: point j's (d, rf) arrive in ONE LDS.64 broadcast (1 wf)
//   instead of 2 shuffles; lanes 0..19 each own a float4 slice of the
//   80-channel feat row (3 line-wavefronts per point, the floor).
// ---------------------------------------------------------------------------
__global__ void __launch_bounds__(256) bev_pool_kernel(
    const float* __restrict__ depth,       // [498432]
    const float* __restrict__ feat,        // [4224, 80]
    const void* __restrict__ ranks_depth,  // [P]
    const void* __restrict__ ranks_feat,   // [P]
    float* __restrict__ out)               // [40000, 80]
{
    __shared__ unsigned long long stage[WPB][BATCH];

    const int warp = (blockIdx.x * blockDim.x + threadIdx.x) >> 5;
    const int wib  = (threadIdx.x >> 5);   // warp in block
    const int lane = threadIdx.x & 31;
    if (warp >= TOTAL_BEV) return;

    const int is64 = detect64(ranks_depth);
    const int lo = g_seg[warp];
    const int hi = g_seg[warp + 1];

    const int  active = (lane < NCH4);
    const int  c4     = active ? lane : 0;   // idle lanes shadow lane 0's line
    const float4* __restrict__ fvc = (const float4*)feat + c4;

    float4 acc = make_float4(0.f, 0.f, 0.f, 0.f);

    for (int p = lo; p < hi; p += BATCH) {
        const int n = min(BATCH, hi - p);

        // ---- stage: coalesced idx loads + depth gather, pack to smem ----
        unsigned long long packed = 0ULL;
        if (lane < n) {
            int   rd = ld_idx32(ranks_depth, p + lane, is64);
            int   rf = ld_idx32(ranks_feat,  p + lane, is64);
            float d  = __ldg(depth + rd);
            packed = ((unsigned long long)__float_as_uint(d) << 32) | (unsigned)rf;
        }
        stage[wib][lane] = packed;
        __syncwarp();

        // ---- consume: 1 LDS.64 broadcast + 1 feat gather per point ----
        if (n == BATCH) {
#pragma unroll 8
            for (int j = 0; j < BATCH; ++j) {
                unsigned long long u = stage[wib][j];
                int   rfj = (int)(unsigned)u;
                float dj  = __uint_as_float((unsigned)(u >> 32));
                float4 f = __ldg(fvc + (size_t)rfj * NCH4);
                acc.x = fmaf(f.x, dj, acc.x); acc.y = fmaf(f.y, dj, acc.y);
                acc.z = fmaf(f.z, dj, acc.z); acc.w = fmaf(f.w, dj, acc.w);
            }
        } else {
            for (int j = 0; j < n; ++j) {
                unsigned long long u = stage[wib][j];
                int   rfj = (int)(unsigned)u;
                float dj  = __uint_as_float((unsigned)(u >> 32));
                float4 f = __ldg(fvc + (size_t)rfj * NCH4);
                acc.x = fmaf(f.x, dj, acc.x); acc.y = fmaf(f.y, dj, acc.y);
                acc.z = fmaf(f.z, dj, acc.z); acc.w = fmaf(f.w, dj, acc.w);
            }
        }
        __syncwarp();   // protect stage[] before next overwrite
    }

    if (active) {
        ((float4*)out)[(size_t)warp * NCH4 + c4] = acc;  // empty bins write zeros
    }
}

// ---------------------------------------------------------------------------
// Launch: inputs (metadata order) = depth, feat, ranks_depth, ranks_feat,
// ranks_bev, interval_starts, interval_lengths, [total_bev]
// interval_* are unused by the reference (segments come from sorted ranks_bev).
// ---------------------------------------------------------------------------
extern "C" void kernel_launch(void* const* d_in, const int* in_sizes, int n_in,
                              void* d_out, int out_size) {
    const float* depth       = (const float*)d_in[0];
    const float* feat        = (const float*)d_in[1];
    const void*  ranks_depth = (const void*)d_in[2];
    const void*  ranks_feat  = (const void*)d_in[3];
    const void*  ranks_bev   = (const void*)d_in[4];
    float*       out         = (float*)d_out;

    build_seg_kernel<<<(TOTAL_BEV + 1 + 255) / 256, 256>>>(ranks_bev, ranks_depth);

    // one warp per bin: 40000 warps, 8 warps/block -> 5000 blocks
    bev_pool_kernel<<<(TOTAL_BEV * 32 + 255) / 256, 256>>>(
        depth, feat, ranks_depth, ranks_feat, out);
}